// round 1
// baseline (speedup 1.0000x reference)
#include <cuda_runtime.h>
#include <math.h>

#define NN 1024
#define EE 32768
#define FF 384
#define HH 64

// Scratch (no allocations allowed)
__device__ float g_q[NN * HH];
__device__ float g_k[NN * HH];
__device__ float g_v[NN * HH];
__device__ float g_A[NN * NN];

// ---------------------------------------------------------------------------
// K1: q/k/v projections.  grid.x = 16 row tiles (64 rows), grid.y = 3 (k,q,v)
// block = 256 threads, each computes 16 outputs of a 64x64 tile.
// ---------------------------------------------------------------------------
__global__ __launch_bounds__(256) void qkv_kernel(
    const float* __restrict__ X,
    const float* __restrict__ Wk,
    const float* __restrict__ Wq,
    const float* __restrict__ Wv)
{
    int rt = blockIdx.x;
    int which = blockIdx.y;
    const float* W = (which == 0) ? Wk : (which == 1) ? Wq : Wv;
    float* O = (which == 0) ? g_k : (which == 1) ? g_q : g_v;

    __shared__ float Xs[64][33];
    __shared__ float Ws[32][65];

    int t = threadIdx.x;
    int col = t & 63;
    int r0 = t >> 6;  // 0..3

    float acc[16];
#pragma unroll
    for (int i = 0; i < 16; i++) acc[i] = 0.f;

    for (int k0 = 0; k0 < FF; k0 += 32) {
#pragma unroll
        for (int i = 0; i < 8; i++) {
            int idx = t + i * 256;
            int r = idx >> 5, c = idx & 31;
            Xs[r][c] = X[(rt * 64 + r) * FF + k0 + c];
        }
#pragma unroll
        for (int i = 0; i < 8; i++) {
            int idx = t + i * 256;
            int r = idx >> 6, c = idx & 63;
            Ws[r][c] = W[(k0 + r) * HH + c];
        }
        __syncthreads();
#pragma unroll
        for (int kk = 0; kk < 32; kk++) {
            float w = Ws[kk][col];
#pragma unroll
            for (int i = 0; i < 16; i++)
                acc[i] = fmaf(Xs[r0 + i * 4][kk], w, acc[i]);
        }
        __syncthreads();
    }
#pragma unroll
    for (int i = 0; i < 16; i++)
        O[(rt * 64 + r0 + i * 4) * HH + col] = acc[i];
}

// ---------------------------------------------------------------------------
// K2: per-edge pre-softmax scatter:
//   A[src,dst] += q[src]·trunc(w*Ek0+(1-w)*Ek1) + k[dst]·trunc(w*Eq0+(1-w)*Eq1)
// one warp per edge; 8 edges per block.
// ---------------------------------------------------------------------------
__global__ __launch_bounds__(256) void edgeA_kernel(
    const int* __restrict__ ei,
    const float* __restrict__ ea,
    const float* __restrict__ Ek,
    const float* __restrict__ Eq,
    const float* __restrict__ bias,
    const float* __restrict__ mult)
{
    int e = blockIdx.x * 8 + (threadIdx.x >> 5);
    int lane = threadIdx.x & 31;
    if (e >= EE) return;
    int src = ei[e];
    int dst = ei[EE + e];
    float x = (ea[e] - bias[0]) * mult[0];
    float w = 1.0f / (1.0f + expf(-x));
    float wm = 1.0f - w;

    float dotsum = 0.f;
#pragma unroll
    for (int i = 0; i < 2; i++) {
        int h = lane + i * 32;
        float rk = truncf(w * Ek[h] + wm * Ek[HH + h]);
        float rq = truncf(w * Eq[h] + wm * Eq[HH + h]);
        dotsum += g_q[src * HH + h] * rk + g_k[dst * HH + h] * rq;
    }
#pragma unroll
    for (int o = 16; o; o >>= 1)
        dotsum += __shfl_xor_sync(0xFFFFFFFFu, dotsum, o);
    if (lane == 0)
        atomicAdd(&g_A[src * NN + dst], dotsum);
}

// ---------------------------------------------------------------------------
// K3: A[i,j] = (A[i,j] + 2*q[i]·k[j]) * (1/sqrt(384)).  In-place on g_A.
// grid = (16,16) 64x64 tiles, block 256.
// ---------------------------------------------------------------------------
__global__ __launch_bounds__(256) void qkT_kernel()
{
    __shared__ float Qs[64][65];
    __shared__ float Ks[64][65];

    int jt = blockIdx.x, it = blockIdx.y;
    int t = threadIdx.x;
    int col = t & 63;
    int r0 = t >> 6;

#pragma unroll
    for (int i = 0; i < 16; i++) {
        int idx = t + i * 256;
        int r = idx >> 6, c = idx & 63;
        Qs[r][c] = g_q[(it * 64 + r) * HH + c];
        Ks[r][c] = g_k[(jt * 64 + r) * HH + c];
    }
    __syncthreads();

    float acc[16];
#pragma unroll
    for (int i = 0; i < 16; i++) acc[i] = 0.f;

#pragma unroll
    for (int h = 0; h < 64; h++) {
        float kb = Ks[col][h];
#pragma unroll
        for (int i = 0; i < 16; i++)
            acc[i] = fmaf(Qs[r0 + i * 4][h], kb, acc[i]);
    }

    const float scale = 1.0f / sqrtf((float)FF);
#pragma unroll
    for (int i = 0; i < 16; i++) {
        int row = it * 64 + r0 + i * 4;
        int c = jt * 64 + col;
        g_A[row * NN + c] = (g_A[row * NN + c] + 2.0f * acc[i]) * scale;
    }
}

// ---------------------------------------------------------------------------
// K4: row softmax over 1024 columns, in-place.  one block (256 thr) per row.
// ---------------------------------------------------------------------------
__global__ __launch_bounds__(256) void softmax_kernel()
{
    int row = blockIdx.x;
    float* a = &g_A[row * NN];
    int t = threadIdx.x;

    float vals[4];
    float m = -INFINITY;
#pragma unroll
    for (int i = 0; i < 4; i++) {
        vals[i] = a[t + i * 256];
        m = fmaxf(m, vals[i]);
    }

    __shared__ float red[256];
    red[t] = m;
    __syncthreads();
    for (int s = 128; s; s >>= 1) {
        if (t < s) red[t] = fmaxf(red[t], red[t + s]);
        __syncthreads();
    }
    m = red[0];
    __syncthreads();

    float sum = 0.f;
#pragma unroll
    for (int i = 0; i < 4; i++) {
        vals[i] = expf(vals[i] - m);
        sum += vals[i];
    }
    red[t] = sum;
    __syncthreads();
    for (int s = 128; s; s >>= 1) {
        if (t < s) red[t] += red[t + s];
        __syncthreads();
    }
    float inv = 1.0f / red[0];
#pragma unroll
    for (int i = 0; i < 4; i++)
        a[t + i * 256] = vals[i] * inv;
}

// ---------------------------------------------------------------------------
// K5: M = A @ v  (writes d_out).  grid = 16 row tiles, block 256.
// ---------------------------------------------------------------------------
__global__ __launch_bounds__(256) void av_kernel(float* __restrict__ out)
{
    __shared__ float As[64][33];
    __shared__ float Vs[32][65];

    int rt = blockIdx.x;
    int t = threadIdx.x;
    int col = t & 63;
    int r0 = t >> 6;

    float acc[16];
#pragma unroll
    for (int i = 0; i < 16; i++) acc[i] = 0.f;

    for (int j0 = 0; j0 < NN; j0 += 32) {
#pragma unroll
        for (int i = 0; i < 8; i++) {
            int idx = t + i * 256;
            int r = idx >> 5, c = idx & 31;
            As[r][c] = g_A[(rt * 64 + r) * NN + j0 + c];
        }
#pragma unroll
        for (int i = 0; i < 8; i++) {
            int idx = t + i * 256;
            int r = idx >> 6, c = idx & 63;
            Vs[r][c] = g_v[(j0 + r) * HH + c];
        }
        __syncthreads();
#pragma unroll
        for (int kk = 0; kk < 32; kk++) {
            float vb = Vs[kk][col];
#pragma unroll
            for (int i = 0; i < 16; i++)
                acc[i] = fmaf(As[r0 + i * 4][kk], vb, acc[i]);
        }
        __syncthreads();
    }
#pragma unroll
    for (int i = 0; i < 16; i++)
        out[(rt * 64 + r0 + i * 4) * HH + col] = acc[i];
}

// ---------------------------------------------------------------------------
// K6: per-edge value correction:
//   M[src,:] += A_softmax[src,dst] * (w*Ev0 + (1-w)*Ev1)
// one warp per edge.
// ---------------------------------------------------------------------------
__global__ __launch_bounds__(256) void edgeV_kernel(
    const int* __restrict__ ei,
    const float* __restrict__ ea,
    const float* __restrict__ Ev,
    const float* __restrict__ bias,
    const float* __restrict__ mult,
    float* __restrict__ out)
{
    int e = blockIdx.x * 8 + (threadIdx.x >> 5);
    int lane = threadIdx.x & 31;
    if (e >= EE) return;
    int src = ei[e];
    int dst = ei[EE + e];
    float x = (ea[e] - bias[0]) * mult[0];
    float w = 1.0f / (1.0f + expf(-x));
    float wm = 1.0f - w;

    float a = g_A[src * NN + dst];
#pragma unroll
    for (int i = 0; i < 2; i++) {
        int h = lane + i * 32;
        float rv = w * Ev[h] + wm * Ev[HH + h];
        atomicAdd(&out[src * HH + h], a * rv);
    }
}

// ---------------------------------------------------------------------------
extern "C" void kernel_launch(void* const* d_in, const int* in_sizes, int n_in,
                              void* d_out, int out_size)
{
    const float* features = (const float*)d_in[0];
    const int* edge_index = (const int*)d_in[1];
    const float* edge_attr = (const float*)d_in[2];
    const float* Wk = (const float*)d_in[3];
    const float* Wq = (const float*)d_in[4];
    const float* Wv = (const float*)d_in[5];
    const float* Ek = (const float*)d_in[6];
    const float* Eq = (const float*)d_in[7];
    const float* Ev = (const float*)d_in[8];
    const float* bias = (const float*)d_in[9];
    const float* mult = (const float*)d_in[10];
    float* out = (float*)d_out;

    float* g_A_ptr = nullptr;
    cudaGetSymbolAddress((void**)&g_A_ptr, g_A);
    cudaMemsetAsync(g_A_ptr, 0, sizeof(float) * NN * NN, 0);

    dim3 qkvGrid(16, 3);
    qkv_kernel<<<qkvGrid, 256>>>(features, Wk, Wq, Wv);

    edgeA_kernel<<<EE / 8, 256>>>(edge_index, edge_attr, Ek, Eq, bias, mult);

    dim3 qkGrid(16, 16);
    qkT_kernel<<<qkGrid, 256>>>();

    softmax_kernel<<<NN, 256>>>();

    av_kernel<<<16, 256>>>(out);

    edgeV_kernel<<<EE / 8, 256>>>(edge_index, edge_attr, Ev, bias, mult, out);
}

// round 11
// speedup vs baseline: 2.6668x; 2.6668x over previous
#include <cuda_runtime.h>
#include <math.h>

#define NN 1024
#define EE 32768
#define FF 384
#define HH 64

// Scratch (no allocations allowed)
__device__ float g_q[NN * HH];
__device__ float g_k[NN * HH];
__device__ float g_v[NN * HH];
__device__ float g_A[NN * NN];
__device__ float g_S1[NN];
__device__ float g_Sw[NN];

// ---------------------------------------------------------------------------
// K1: q/k/v projections, split-K.  grid (32 row-tiles of 32, 3 mats, 2 ksplit)
// block 256: each thread 2 rows x 4 cols, atomicAdd epilogue (outputs zeroed).
// ---------------------------------------------------------------------------
__global__ __launch_bounds__(256) void qkv_kernel(
    const float* __restrict__ X,
    const float* __restrict__ Wk,
    const float* __restrict__ Wq,
    const float* __restrict__ Wv)
{
    int rt = blockIdx.x;          // 32-row tile
    int which = blockIdx.y;
    int kz = blockIdx.z;          // k-chunk of 192
    const float* W = (which == 0) ? Wk : (which == 1) ? Wq : Wv;
    float* O = (which == 0) ? g_k : (which == 1) ? g_q : g_v;

    __shared__ float Xs[32][33];
    __shared__ float Ws[32][65];

    int t = threadIdx.x;
    int tx = t & 15;              // col group: cols tx*4..tx*4+3
    int ty = t >> 4;              // row group: rows ty*2, ty*2+1

    float acc[2][4];
#pragma unroll
    for (int i = 0; i < 2; i++)
#pragma unroll
        for (int j = 0; j < 4; j++) acc[i][j] = 0.f;

    int kbase = kz * 192;
    for (int k0 = 0; k0 < 192; k0 += 32) {
#pragma unroll
        for (int i = 0; i < 4; i++) {
            int idx = t + i * 256;
            int r = idx >> 5, c = idx & 31;
            Xs[r][c] = X[(rt * 32 + r) * FF + kbase + k0 + c];
        }
#pragma unroll
        for (int i = 0; i < 8; i++) {
            int idx = t + i * 256;
            int r = idx >> 6, c = idx & 63;
            Ws[r][c] = W[(kbase + k0 + r) * HH + c];
        }
        __syncthreads();
#pragma unroll
        for (int kk = 0; kk < 32; kk++) {
            float x0 = Xs[ty * 2 + 0][kk];
            float x1 = Xs[ty * 2 + 1][kk];
#pragma unroll
            for (int j = 0; j < 4; j++) {
                float w = Ws[kk][tx * 4 + j];
                acc[0][j] = fmaf(x0, w, acc[0][j]);
                acc[1][j] = fmaf(x1, w, acc[1][j]);
            }
        }
        __syncthreads();
    }
#pragma unroll
    for (int i = 0; i < 2; i++)
#pragma unroll
        for (int j = 0; j < 4; j++)
            atomicAdd(&O[(rt * 32 + ty * 2 + i) * HH + tx * 4 + j], acc[i][j]);
}

// ---------------------------------------------------------------------------
// K2: per-edge pre-softmax scatter (exact expf: w feeds trunc):
//   A[src,dst] += q[src]·trunc(w*Ek0+(1-w)*Ek1) + k[dst]·trunc(w*Eq0+(1-w)*Eq1)
// ---------------------------------------------------------------------------
__global__ __launch_bounds__(256) void edgeA_kernel(
    const int* __restrict__ ei,
    const float* __restrict__ ea,
    const float* __restrict__ Ek,
    const float* __restrict__ Eq,
    const float* __restrict__ bias,
    const float* __restrict__ mult)
{
    int e = blockIdx.x * 8 + (threadIdx.x >> 5);
    int lane = threadIdx.x & 31;
    if (e >= EE) return;
    int src = ei[e];
    int dst = ei[EE + e];
    float x = (ea[e] - bias[0]) * mult[0];
    float w = 1.0f / (1.0f + expf(-x));
    float wm = 1.0f - w;

    float dotsum = 0.f;
#pragma unroll
    for (int i = 0; i < 2; i++) {
        int h = lane + i * 32;
        float rk = truncf(w * Ek[h] + wm * Ek[HH + h]);
        float rq = truncf(w * Eq[h] + wm * Eq[HH + h]);
        dotsum += g_q[src * HH + h] * rk + g_k[dst * HH + h] * rq;
    }
#pragma unroll
    for (int o = 16; o; o >>= 1)
        dotsum += __shfl_xor_sync(0xFFFFFFFFu, dotsum, o);
    if (lane == 0)
        atomicAdd(&g_A[src * NN + dst], dotsum);
}

// ---------------------------------------------------------------------------
// K3: A[i,j] = (A[i,j] + 2*q[i]·k[j]) / sqrt(384).  grid (16,16), 4x4/thread.
// ---------------------------------------------------------------------------
__global__ __launch_bounds__(256) void qkT_kernel()
{
    __shared__ float Qs[64][65];
    __shared__ float Ks[64][65];

    int jt = blockIdx.x, it = blockIdx.y;
    int t = threadIdx.x;
    int tx = t & 15;   // cols tx*4..+3
    int ty = t >> 4;   // rows ty*4..+3

#pragma unroll
    for (int i = 0; i < 16; i++) {
        int idx = t + i * 256;
        int r = idx >> 6, c = idx & 63;
        Qs[r][c] = g_q[(it * 64 + r) * HH + c];
        Ks[r][c] = g_k[(jt * 64 + r) * HH + c];
    }
    __syncthreads();

    float acc[4][4];
#pragma unroll
    for (int i = 0; i < 4; i++)
#pragma unroll
        for (int j = 0; j < 4; j++) acc[i][j] = 0.f;

#pragma unroll
    for (int h = 0; h < 64; h++) {
        float qv[4], kv[4];
#pragma unroll
        for (int i = 0; i < 4; i++) qv[i] = Qs[ty * 4 + i][h];
#pragma unroll
        for (int j = 0; j < 4; j++) kv[j] = Ks[tx * 4 + j][h];
#pragma unroll
        for (int i = 0; i < 4; i++)
#pragma unroll
            for (int j = 0; j < 4; j++)
                acc[i][j] = fmaf(qv[i], kv[j], acc[i][j]);
    }

    const float scale = 1.0f / sqrtf((float)FF);
#pragma unroll
    for (int i = 0; i < 4; i++) {
        int row = it * 64 + ty * 4 + i;
        float4* p = (float4*)&g_A[row * NN + jt * 64 + tx * 4];
        float4 a = *p;
        a.x = (a.x + 2.0f * acc[i][0]) * scale;
        a.y = (a.y + 2.0f * acc[i][1]) * scale;
        a.z = (a.z + 2.0f * acc[i][2]) * scale;
        a.w = (a.w + 2.0f * acc[i][3]) * scale;
        *p = a;
    }
}

// ---------------------------------------------------------------------------
// K4: row softmax, warp per row, float4 loads, shuffle-only reductions.
// grid 128 x 256 threads (8 rows per block).
// ---------------------------------------------------------------------------
__global__ __launch_bounds__(256) void softmax_kernel()
{
    int warp = (blockIdx.x * 256 + threadIdx.x) >> 5;
    int lane = threadIdx.x & 31;
    float4* a = (float4*)&g_A[warp * NN];

    float4 v[8];
    float m = -INFINITY;
#pragma unroll
    for (int i = 0; i < 8; i++) {
        v[i] = a[lane + i * 32];
        m = fmaxf(m, fmaxf(fmaxf(v[i].x, v[i].y), fmaxf(v[i].z, v[i].w)));
    }
#pragma unroll
    for (int o = 16; o; o >>= 1)
        m = fmaxf(m, __shfl_xor_sync(0xFFFFFFFFu, m, o));

    float sum = 0.f;
#pragma unroll
    for (int i = 0; i < 8; i++) {
        v[i].x = __expf(v[i].x - m);
        v[i].y = __expf(v[i].y - m);
        v[i].z = __expf(v[i].z - m);
        v[i].w = __expf(v[i].w - m);
        sum += v[i].x + v[i].y + v[i].z + v[i].w;
    }
#pragma unroll
    for (int o = 16; o; o >>= 1)
        sum += __shfl_xor_sync(0xFFFFFFFFu, sum, o);

    float inv = 1.0f / sum;
#pragma unroll
    for (int i = 0; i < 8; i++) {
        v[i].x *= inv; v[i].y *= inv; v[i].z *= inv; v[i].w *= inv;
        a[lane + i * 32] = v[i];
    }
}

// ---------------------------------------------------------------------------
// K5: M = A @ v, split-K.  grid (16 row-tiles, 8 k-chunks of 128).
// 4x4 register tile; atomicAdd into zeroed out.
// ---------------------------------------------------------------------------
__global__ __launch_bounds__(256) void av_kernel(float* __restrict__ out)
{
    __shared__ float As[64][33];
    __shared__ float Vs[32][65];

    int rt = blockIdx.x;
    int kz = blockIdx.y;
    int t = threadIdx.x;
    int tx = t & 15;
    int ty = t >> 4;

    float acc[4][4];
#pragma unroll
    for (int i = 0; i < 4; i++)
#pragma unroll
        for (int j = 0; j < 4; j++) acc[i][j] = 0.f;

    for (int j0 = kz * 128; j0 < kz * 128 + 128; j0 += 32) {
#pragma unroll
        for (int i = 0; i < 8; i++) {
            int idx = t + i * 256;
            int r = idx >> 5, c = idx & 31;
            As[r][c] = g_A[(rt * 64 + r) * NN + j0 + c];
        }
#pragma unroll
        for (int i = 0; i < 8; i++) {
            int idx = t + i * 256;
            int r = idx >> 6, c = idx & 63;
            Vs[r][c] = g_v[(j0 + r) * HH + c];
        }
        __syncthreads();
#pragma unroll
        for (int kk = 0; kk < 32; kk++) {
            float av[4], vv[4];
#pragma unroll
            for (int i = 0; i < 4; i++) av[i] = As[ty * 4 + i][kk];
#pragma unroll
            for (int j = 0; j < 4; j++) vv[j] = Vs[kk][tx * 4 + j];
#pragma unroll
            for (int i = 0; i < 4; i++)
#pragma unroll
                for (int j = 0; j < 4; j++)
                    acc[i][j] = fmaf(av[i], vv[j], acc[i][j]);
        }
        __syncthreads();
    }
#pragma unroll
    for (int i = 0; i < 4; i++)
#pragma unroll
        for (int j = 0; j < 4; j++)
            atomicAdd(&out[(rt * 64 + ty * 4 + i) * HH + tx * 4 + j], acc[i][j]);
}

// ---------------------------------------------------------------------------
// K6: per-edge scalar sums: S1[src] += A[src,dst], Sw[src] += A[src,dst]*w.
// (rv is linear in w, so the 64-dim edge-value correction collapses to rank-1.)
// ---------------------------------------------------------------------------
__global__ __launch_bounds__(256) void edgeS_kernel(
    const int* __restrict__ ei,
    const float* __restrict__ ea,
    const float* __restrict__ bias,
    const float* __restrict__ mult)
{
    int e = blockIdx.x * 256 + threadIdx.x;
    if (e >= EE) return;
    int src = ei[e];
    int dst = ei[EE + e];
    float x = (ea[e] - bias[0]) * mult[0];
    float w = 1.0f / (1.0f + __expf(-x));
    float a = g_A[src * NN + dst];
    atomicAdd(&g_S1[src], a);
    atomicAdd(&g_Sw[src], a * w);
}

// ---------------------------------------------------------------------------
// K7: out[i,h] += S1[i]*Ev1[h] + Sw[i]*(Ev0[h]-Ev1[h]).  grid 256 x 256.
// ---------------------------------------------------------------------------
__global__ __launch_bounds__(256) void outfix_kernel(
    const float* __restrict__ Ev, float* __restrict__ out)
{
    int t = threadIdx.x;
    int h = t & 63;
    int i = blockIdx.x * 4 + (t >> 6);
    float e0 = Ev[h], e1 = Ev[HH + h];
    out[i * HH + h] += g_S1[i] * e1 + g_Sw[i] * (e0 - e1);
}

// ---------------------------------------------------------------------------
extern "C" void kernel_launch(void* const* d_in, const int* in_sizes, int n_in,
                              void* d_out, int out_size)
{
    const float* features = (const float*)d_in[0];
    const int* edge_index = (const int*)d_in[1];
    const float* edge_attr = (const float*)d_in[2];
    const float* Wk = (const float*)d_in[3];
    const float* Wq = (const float*)d_in[4];
    const float* Wv = (const float*)d_in[5];
    const float* Ek = (const float*)d_in[6];
    const float* Eq = (const float*)d_in[7];
    const float* Ev = (const float*)d_in[8];
    const float* bias = (const float*)d_in[9];
    const float* mult = (const float*)d_in[10];
    float* out = (float*)d_out;

    void* p;
    cudaGetSymbolAddress(&p, g_A);  cudaMemsetAsync(p, 0, sizeof(float) * NN * NN, 0);
    cudaGetSymbolAddress(&p, g_q);  cudaMemsetAsync(p, 0, sizeof(float) * NN * HH, 0);
    cudaGetSymbolAddress(&p, g_k);  cudaMemsetAsync(p, 0, sizeof(float) * NN * HH, 0);
    cudaGetSymbolAddress(&p, g_v);  cudaMemsetAsync(p, 0, sizeof(float) * NN * HH, 0);
    cudaGetSymbolAddress(&p, g_S1); cudaMemsetAsync(p, 0, sizeof(float) * NN, 0);
    cudaGetSymbolAddress(&p, g_Sw); cudaMemsetAsync(p, 0, sizeof(float) * NN, 0);
    cudaMemsetAsync(out, 0, sizeof(float) * NN * HH, 0);

    qkv_kernel<<<dim3(32, 3, 2), 256>>>(features, Wk, Wq, Wv);
    edgeA_kernel<<<EE / 8, 256>>>(edge_index, edge_attr, Ek, Eq, bias, mult);
    qkT_kernel<<<dim3(16, 16), 256>>>();
    softmax_kernel<<<128, 256>>>();
    av_kernel<<<dim3(16, 8), 256>>>(out);
    edgeS_kernel<<<EE / 256, 256>>>(edge_index, edge_attr, bias, mult);
    outfix_kernel<<<NN / 4, 256>>>(Ev, out);
}